// round 10
// baseline (speedup 1.0000x reference)
#include <cuda_runtime.h>
#include <cuda_bf16.h>

#define HH 256
#define WW 256
#define BB 4
#define EPS_ 1e-5f

// ================= device-global scratch (no runtime allocation) =================
__device__ __align__(16) __nv_bfloat16 g_hiA[4*256*256*64];
__device__ __align__(16) __nv_bfloat16 g_loA[4*256*256*64];
__device__ __align__(16) __nv_bfloat16 g_hiB[4*256*256*64];
__device__ __align__(16) __nv_bfloat16 g_loB[4*256*256*64];
// hidden weights MMA-ready: [tap 9][split 2][8KB: 64 oc rows x 128B (64 ic bf16), SW128]
__device__ __align__(16) unsigned char g_wmma[9*16384];
__device__ __align__(16) float g_wT_in[3*9*64];     // [ic][tap][oc]
__device__ __align__(16) float g_wT_out[64*9*4];    // [ic][tap][oc pad4]
__device__ float g_bf_in[64];
__device__ float g_bf_h [64];
__device__ float g_bf_out[4];

// ================= helpers =================
__device__ __forceinline__ float selu_f(float x) {
    return x > 0.f ? 1.0507009873554805f * x
                   : 1.7580993408473766f * expm1f(x);
}
__device__ __forceinline__ unsigned smem_u32(const void* p) {
    unsigned a;
    asm("{ .reg .u64 t; cvta.to.shared.u64 t, %1; cvt.u32.u64 %0, t; }" : "=r"(a) : "l"(p));
    return a;
}
#define SWZ128(o) ((o) ^ (((o) >> 3) & 0x70))

__device__ __forceinline__ void ldm4(unsigned* r, unsigned addr) {
    asm volatile("ldmatrix.sync.aligned.m8n8.x4.shared.b16 {%0,%1,%2,%3}, [%4];"
        : "=r"(r[0]), "=r"(r[1]), "=r"(r[2]), "=r"(r[3]) : "r"(addr));
}
__device__ __forceinline__ void mma16816(float* d, const unsigned* a, const unsigned* b) {
    asm volatile("mma.sync.aligned.m16n8k16.row.col.f32.bf16.bf16.f32 "
        "{%0,%1,%2,%3}, {%4,%5,%6,%7}, {%8,%9}, {%0,%1,%2,%3};"
        : "+f"(d[0]), "+f"(d[1]), "+f"(d[2]), "+f"(d[3])
        : "r"(a[0]), "r"(a[1]), "r"(a[2]), "r"(a[3]), "r"(b[0]), "r"(b[1]));
}
__device__ __forceinline__ unsigned pack_bf2(float a, float b) {
    __nv_bfloat16 ha = __float2bfloat16_rn(a);
    __nv_bfloat16 hb = __float2bfloat16_rn(b);
    return (unsigned)reinterpret_cast<unsigned short&>(ha)
         | ((unsigned)reinterpret_cast<unsigned short&>(hb) << 16);
}

// ================= prep: BN fold + weight transpose + bf16 split-swizzle =================
__global__ void prep_kernel(
    const float* __restrict__ w_in, const float* __restrict__ b_in,
    const float* __restrict__ g_in, const float* __restrict__ be_in,
    const float* __restrict__ m_in, const float* __restrict__ v_in,
    const float* __restrict__ w_h,  const float* __restrict__ b_h,
    const float* __restrict__ g_h,  const float* __restrict__ be_h,
    const float* __restrict__ m_h,  const float* __restrict__ v_h,
    const float* __restrict__ w_out,const float* __restrict__ b_out,
    const float* __restrict__ g_out,const float* __restrict__ be_out,
    const float* __restrict__ m_out,const float* __restrict__ v_out)
{
    int tid = blockIdx.x * blockDim.x + threadIdx.x;
    int stride = gridDim.x * blockDim.x;
    for (int i = tid; i < 9*64*64; i += stride) {
        int tap = i >> 12;
        int rem = i & 4095;
        int oc = rem >> 6, ic = rem & 63;
        float s = g_h[oc] * rsqrtf(v_h[oc] + EPS_);
        float w = w_h[(oc*64 + ic)*9 + tap] * s;
        __nv_bfloat16 h = __float2bfloat16_rn(w);
        float lof = w - __bfloat162float(h);
        __nv_bfloat16 l = __float2bfloat16_rn(lof);
        unsigned off = SWZ128((unsigned)(oc*128 + ic*2));
        *(__nv_bfloat16*)(g_wmma + tap*16384 + off) = h;
        *(__nv_bfloat16*)(g_wmma + tap*16384 + 8192 + off) = l;
    }
    for (int i = tid; i < 64*27; i += stride) {
        int oc = i / 27; int rem = i - oc*27;
        int ic = rem / 9; int t = rem - ic*9;
        float s = g_in[oc] * rsqrtf(v_in[oc] + EPS_);
        g_wT_in[(ic*9+t)*64 + oc] = w_in[i] * s;
    }
    for (int i = tid; i < 3*576; i += stride) {
        int oc = i / 576; int rem = i - oc*576;
        int ic = rem / 9; int t = rem - ic*9;
        float s = g_out[oc] * rsqrtf(v_out[oc] + EPS_);
        g_wT_out[(ic*9+t)*4 + oc] = w_out[i] * s;
    }
    if (tid < 64) {
        g_bf_in[tid] = (b_in[tid] - m_in[tid]) * (g_in[tid]*rsqrtf(v_in[tid]+EPS_)) + be_in[tid];
        g_bf_h[tid]  = (b_h[tid]  - m_h[tid])  * (g_h[tid] *rsqrtf(v_h[tid] +EPS_)) + be_h[tid];
    }
    if (tid < 3)
        g_bf_out[tid] = (b_out[tid] - m_out[tid]) * (g_out[tid]*rsqrtf(v_out[tid]+EPS_)) + be_out[tid];
}

// ================= layer 0: NCHW X (3ch) -> hi/lo bf16 NHWC 64 =================
__global__ void __launch_bounds__(256) layer_in_kernel(const float* __restrict__ X)
{
    __shared__ __align__(16) float ws[27*64];
    __shared__ float bs[64];
    int tid = threadIdx.x;
    for (int i = tid; i < 27*64; i += 256) ws[i] = g_wT_in[i];
    if (tid < 64) bs[tid] = g_bf_in[tid];
    __syncthreads();

    int b  = blockIdx.z;
    int gy = blockIdx.y * 16 + (tid >> 4);
    int gx = blockIdx.x * 16 + (tid & 15);

    float patch[27];
    #pragma unroll
    for (int ic = 0; ic < 3; ic++)
        #pragma unroll
        for (int ky = 0; ky < 3; ky++)
            #pragma unroll
            for (int kx = 0; kx < 3; kx++) {
                int y = gy + ky - 1, x = gx + kx - 1;
                float v = 0.f;
                if ((unsigned)y < HH && (unsigned)x < WW)
                    v = X[((b*3 + ic)*HH + y)*WW + x];
                patch[(ic*3+ky)*3+kx] = v;
            }

    float acc[64];
    #pragma unroll
    for (int k = 0; k < 64; k++) acc[k] = bs[k];
    #pragma unroll
    for (int q = 0; q < 27; q++) {
        float xv = patch[q];
        const float* wr = &ws[q*64];
        #pragma unroll
        for (int k = 0; k < 64; k += 4) {
            float4 w = *(const float4*)(wr + k);
            acc[k]   += xv*w.x; acc[k+1] += xv*w.y;
            acc[k+2] += xv*w.z; acc[k+3] += xv*w.w;
        }
    }
    size_t pb = (((size_t)(b*HH) + gy)*WW + gx)*64;
    #pragma unroll
    for (int g = 0; g < 8; g++) {
        float v[8];
        #pragma unroll
        for (int c = 0; c < 8; c++) v[c] = selu_f(acc[g*8+c]);
        unsigned uh[4], ul[4];
        #pragma unroll
        for (int c2 = 0; c2 < 4; c2++) {
            float a = v[2*c2], bb = v[2*c2+1];
            __nv_bfloat16 ha = __float2bfloat16_rn(a), hb = __float2bfloat16_rn(bb);
            float la = a - __bfloat162float(ha), lb = bb - __bfloat162float(hb);
            uh[c2] = (unsigned)reinterpret_cast<unsigned short&>(ha)
                   | ((unsigned)reinterpret_cast<unsigned short&>(hb) << 16);
            ul[c2] = pack_bf2(la, lb);
        }
        *(uint4*)(g_hiA + pb + g*8) = make_uint4(uh[0],uh[1],uh[2],uh[3]);
        *(uint4*)(g_loA + pb + g*8) = make_uint4(ul[0],ul[1],ul[2],ul[3]);
    }
}

// ================= hidden layers: mma.sync bf16-split implicit conv =================
// CTA 16x16 px x 64 oc, 8 warps, 2 CTAs/SM. Single smem weight buffer;
// next tap's weights prefetched into REGISTERS during current tap compute.
#define SM_BIAS  0
#define SM_W     1024                /* single 16KB tap buffer */
#define SM_X     (1024 + 16384)      /* 17408, 1024-aligned */
#define X_SPLIT  41984               /* >= 324px*128B, 1024-aligned */
#define HID_SMEM (SM_X + 2*X_SPLIT)  /* 101376 -> 2 CTAs/SM */
#define PXSTR    68                  /* epilogue f32 stride per pixel */

__global__ void __launch_bounds__(256, 2) hidden_mma_kernel(int flip)
{
    extern __shared__ __align__(1024) unsigned char smem[];
    unsigned sb = smem_u32(smem);
    int tid = threadIdx.x;
    int w = tid >> 5, lane = tid & 31;

    const __nv_bfloat16* __restrict__ shi = flip ? g_hiB : g_hiA;
    const __nv_bfloat16* __restrict__ slo = flip ? g_loB : g_loA;
    __nv_bfloat16* __restrict__ dhi = flip ? g_hiA : g_hiB;
    __nv_bfloat16* __restrict__ dlo = flip ? g_loA : g_loB;

    int b  = blockIdx.z;
    int y0 = blockIdx.y * 16;
    int x0 = blockIdx.x * 16;

    if (tid < 64) ((float*)smem)[tid] = g_bf_h[tid];

    // ---- stage weights tap 0 directly, plus input tiles ----
    {
        const uint4* wsrc = (const uint4*)(g_wmma);
        uint4* wdst = (uint4*)(smem + SM_W);
        #pragma unroll
        for (int i = 0; i < 4; i++) wdst[tid + i*256] = wsrc[tid + i*256];
    }
    // ---- stage input tile: 2 splits x 18x18 px x 128B, SW128 per tile ----
    for (int i = tid; i < 5184; i += 256) {
        int split = i >= 2592;
        int r = split ? i - 2592 : i;
        int pxi = r >> 3, g = r & 7;
        int iy = pxi / 18, ix = pxi - iy*18;
        int gy = y0 - 1 + iy, gx = x0 - 1 + ix;
        uint4 v = make_uint4(0,0,0,0);
        if ((unsigned)gy < HH && (unsigned)gx < WW) {
            const __nv_bfloat16* sp = (split ? slo : shi) + (((size_t)(b*HH) + gy)*WW + gx)*64;
            v = *((const uint4*)sp + g);
        }
        unsigned rel = (unsigned)(pxi*128 + g*16);
        *(uint4*)(smem + SM_X + split*X_SPLIT + SWZ128(rel)) = v;
    }
    __syncthreads();

    float acc[2][8][4];
    #pragma unroll
    for (int mt = 0; mt < 2; mt++)
        #pragma unroll
        for (int nt = 0; nt < 8; nt++)
            #pragma unroll
            for (int q = 0; q < 4; q++) acc[mt][nt][q] = 0.f;

    int amat = lane >> 3, arow = lane & 7;
    int a_frow = ((amat & 1) << 3) + arow;   // A: fragment row (pixel)
    int a_kg   = amat >> 1;                  // A: k granule (16B)
    int b_roff = ((amat >> 1) << 3) + arow;  // B: oc row offset
    int b_kg   = amat & 1;                   // B: k granule

    uint4 wreg[4];

    #pragma unroll 1
    for (int tap = 0; tap < 9; tap++) {
        // issue next tap's weight loads early; latency hidden under MMA compute
        if (tap < 8) {
            const uint4* wsrc = (const uint4*)(g_wmma + (tap+1)*16384);
            #pragma unroll
            for (int i = 0; i < 4; i++) wreg[i] = wsrc[tid + i*256];
        }

        int dy = tap / 3, dx = tap - dy*3;
        unsigned wb = sb + SM_W;

        #pragma unroll
        for (int ks = 0; ks < 4; ks++) {
            unsigned Ah[2][4], Al[2][4];
            #pragma unroll
            for (int mt = 0; mt < 2; mt++) {
                int iy  = 2*w + mt + dy;
                int pxi = iy*18 + dx + a_frow;
                unsigned rel = (unsigned)(pxi*128 + ks*32 + a_kg*16);
                rel ^= (unsigned)((pxi & 7) << 4);
                ldm4(Ah[mt], sb + SM_X + rel);
                ldm4(Al[mt], sb + SM_X + X_SPLIT + rel);
            }
            #pragma unroll
            for (int ntp = 0; ntp < 4; ntp++) {
                unsigned Bh4[4], Bl4[4];
                int brow = ntp*16 + b_roff;
                unsigned rel = (unsigned)(brow*128 + ks*32 + b_kg*16);
                rel ^= (unsigned)((brow & 7) << 4);
                ldm4(Bh4, wb + rel);
                ldm4(Bl4, wb + 8192 + rel);
                #pragma unroll
                for (int mt = 0; mt < 2; mt++)
                    #pragma unroll
                    for (int h = 0; h < 2; h++) {
                        float* ac = acc[mt][ntp*2 + h];
                        mma16816(ac, Ah[mt], &Bh4[h*2]);   // xh*wh
                        mma16816(ac, Ah[mt], &Bl4[h*2]);   // xh*wl
                        mma16816(ac, Al[mt], &Bh4[h*2]);   // xl*wh
                    }
            }
        }

        // swap in prefetched weights: short serial section (4 STS.128 + 2 bar)
        if (tap < 8) {
            __syncthreads();   // all warps done reading current tap
            uint4* wdst = (uint4*)(smem + SM_W);
            #pragma unroll
            for (int i = 0; i < 4; i++) wdst[tid + i*256] = wreg[i];
            __syncthreads();   // staged before anyone reads
        }
    }

    // ---- epilogue: fragments -> smem f32 (padded) -> bias+selu -> hi/lo bf16 ----
    __syncthreads();   // all warps done reading xs; reuse as f32 staging
    float* fs = (float*)(smem + SM_X);
    #pragma unroll
    for (int mt = 0; mt < 2; mt++) {
        int prow = 2*w + mt;
        #pragma unroll
        for (int nt = 0; nt < 8; nt++) {
            int oc = nt*8 + 2*(lane & 3);
            int p0 = (prow*16 + (lane >> 2)) * PXSTR + oc;
            int p1 = (prow*16 + (lane >> 2) + 8) * PXSTR + oc;
            *(float2*)&fs[p0] = make_float2(acc[mt][nt][0], acc[mt][nt][1]);
            *(float2*)&fs[p1] = make_float2(acc[mt][nt][2], acc[mt][nt][3]);
        }
    }
    __syncthreads();

    {
        const float* bias = (const float*)smem;
        int ly = tid >> 4, lx = tid & 15;
        const float* fp = fs + tid * PXSTR;
        size_t pb = (((size_t)(b*HH) + (y0 + ly))*WW + (x0 + lx))*64;
        #pragma unroll
        for (int g = 0; g < 8; g++) {
            float4 v0 = *(const float4*)(fp + g*8);
            float4 v1 = *(const float4*)(fp + g*8 + 4);
            float v[8] = {v0.x, v0.y, v0.z, v0.w, v1.x, v1.y, v1.z, v1.w};
            unsigned uh[4], ul[4];
            #pragma unroll
            for (int c2 = 0; c2 < 4; c2++) {
                float a = selu_f(v[2*c2]   + bias[g*8 + 2*c2]);
                float c = selu_f(v[2*c2+1] + bias[g*8 + 2*c2 + 1]);
                __nv_bfloat16 ha = __float2bfloat16_rn(a), hc = __float2bfloat16_rn(c);
                float la = a - __bfloat162float(ha), lc = c - __bfloat162float(hc);
                uh[c2] = (unsigned)reinterpret_cast<unsigned short&>(ha)
                       | ((unsigned)reinterpret_cast<unsigned short&>(hc) << 16);
                ul[c2] = pack_bf2(la, lc);
            }
            *(uint4*)(dhi + pb + g*8) = make_uint4(uh[0],uh[1],uh[2],uh[3]);
            *(uint4*)(dlo + pb + g*8) = make_uint4(ul[0],ul[1],ul[2],ul[3]);
        }
    }
}

// ================= output layer + zero-interpolation residual =================
#define XP2 20
__global__ void __launch_bounds__(256) layer_out_kernel(const float* __restrict__ X,
                                                        float* __restrict__ out)
{
    __shared__ __align__(16) float xs[16*18*XP2];
    __shared__ __align__(16) float ws[576*4];
    int tid = threadIdx.x;
    for (int i = tid; i < 2304; i += 256) ws[i] = g_wT_out[i];

    int b   = blockIdx.z;
    int ty0 = blockIdx.y*16, tx0 = blockIdx.x*16;
    int row = tid >> 4, col = tid & 15;
    float a0 = 0.f, a1 = 0.f, a2 = 0.f;

    for (int c0 = 0; c0 < 64; c0 += 16) {
        __syncthreads();
        for (int i = tid; i < 1296; i += 256) {
            int q  = i & 3;
            int p  = i >> 2;
            int yy = p / 18, xx = p - yy*18;
            int gy = ty0 + yy - 1, gx = tx0 + xx - 1;
            float v0=0.f, v1=0.f, v2=0.f, v3=0.f;
            if ((unsigned)gy < HH && (unsigned)gx < WW) {
                size_t idx = (((size_t)(b*HH) + gy)*WW + gx)*64 + c0 + q*4;
                uint2 hv = *(const uint2*)(g_hiA + idx);
                uint2 lv = *(const uint2*)(g_loA + idx);
                __nv_bfloat162 h0 = *(__nv_bfloat162*)&hv.x, h1 = *(__nv_bfloat162*)&hv.y;
                __nv_bfloat162 l0 = *(__nv_bfloat162*)&lv.x, l1 = *(__nv_bfloat162*)&lv.y;
                v0 = __bfloat162float(h0.x) + __bfloat162float(l0.x);
                v1 = __bfloat162float(h0.y) + __bfloat162float(l0.y);
                v2 = __bfloat162float(h1.x) + __bfloat162float(l1.x);
                v3 = __bfloat162float(h1.y) + __bfloat162float(l1.y);
            }
            float* d = xs + (q*4)*(18*XP2) + yy*XP2 + xx;
            d[0] = v0; d[18*XP2] = v1; d[2*18*XP2] = v2; d[3*18*XP2] = v3;
        }
        __syncthreads();
        for (int icL = 0; icL < 16; icL++) {
            const float* xpl = xs + icL*18*XP2 + row*XP2 + col;
            const float* wr  = ws + (c0+icL)*36;
            #pragma unroll
            for (int tap = 0; tap < 9; tap++) {
                float xv = xpl[(tap/3)*XP2 + (tap%3)];
                float4 w = *(const float4*)(wr + tap*4);
                a0 += xv*w.x; a1 += xv*w.y; a2 += xv*w.z;
            }
        }
    }
    float vv[3];
    vv[0] = selu_f(a0 + g_bf_out[0]);
    vv[1] = selu_f(a1 + g_bf_out[1]);
    vv[2] = selu_f(a2 + g_bf_out[2]);

    int gy = ty0 + row, gx = tx0 + col;
    #pragma unroll
    for (int c = 0; c < 3; c++) {
        size_t idx = ((size_t)(b*3+c)*HH + gy)*WW + gx;
        float xc = X[idx];
        float res;
        if (xc == 0.f) {
            float lf = (gx > 0)    ? X[idx-1]  : 0.f;
            float rt = (gx < WW-1) ? X[idx+1]  : 0.f;
            float tp = (gy > 0)    ? X[idx-WW] : 0.f;
            float bt = (gy < HH-1) ? X[idx+WW] : 0.f;
            float sum = lf + rt + tp + bt;
            float cnt = (float)(lf>0.f) + (float)(rt>0.f) + (float)(tp>0.f) + (float)(bt>0.f);
            res = (cnt > 0.f) ? sum / cnt : 0.f;
        } else {
            res = xc;
        }
        out[idx] = vv[c] + res;
    }
}

// ================= launch =================
extern "C" void kernel_launch(void* const* d_in, const int* in_sizes, int n_in,
                              void* d_out, int out_size)
{
    const float* X      = (const float*)d_in[0];
    const float* w_in   = (const float*)d_in[1];
    const float* b_in   = (const float*)d_in[2];
    const float* g_in   = (const float*)d_in[3];
    const float* be_in  = (const float*)d_in[4];
    const float* m_in   = (const float*)d_in[5];
    const float* v_in   = (const float*)d_in[6];
    const float* w_h    = (const float*)d_in[7];
    const float* b_h    = (const float*)d_in[8];
    const float* g_h    = (const float*)d_in[9];
    const float* be_h   = (const float*)d_in[10];
    const float* m_h    = (const float*)d_in[11];
    const float* v_h    = (const float*)d_in[12];
    const float* w_out  = (const float*)d_in[13];
    const float* b_out  = (const float*)d_in[14];
    const float* g_out  = (const float*)d_in[15];
    const float* be_out = (const float*)d_in[16];
    const float* m_out  = (const float*)d_in[17];
    const float* v_out  = (const float*)d_in[18];
    float* out = (float*)d_out;

    cudaFuncSetAttribute(hidden_mma_kernel,
                         cudaFuncAttributeMaxDynamicSharedMemorySize, HID_SMEM);

    prep_kernel<<<144, 256>>>(w_in, b_in, g_in, be_in, m_in, v_in,
                              w_h, b_h, g_h, be_h, m_h, v_h,
                              w_out, b_out, g_out, be_out, m_out, v_out);
    layer_in_kernel<<<dim3(16,16,4), 256>>>(X);
    int flip = 0;
    for (int l = 0; l < 18; l++) {
        hidden_mma_kernel<<<dim3(16,16,4), 256, HID_SMEM>>>(flip);
        flip ^= 1;
    }
    layer_out_kernel<<<dim3(16,16,4), 256>>>(X, out);
}

// round 12
// speedup vs baseline: 1.5837x; 1.5837x over previous
#include <cuda_runtime.h>
#include <cuda_bf16.h>

#define HH 256
#define WW 256
#define BB 4
#define EPS_ 1e-5f

// ================= device-global scratch (no runtime allocation) =================
__device__ __align__(16) __nv_bfloat16 g_hiA[4*256*256*64];
__device__ __align__(16) __nv_bfloat16 g_loA[4*256*256*64];
__device__ __align__(16) __nv_bfloat16 g_hiB[4*256*256*64];
__device__ __align__(16) __nv_bfloat16 g_loB[4*256*256*64];
// hidden weights in per-lane MMA B-fragment order:
// [tap 9][ks 4][ntile 8][lane 32] x uint4 {bh0, bh1, bl0, bl1}
__device__ __align__(16) uint4 g_wfragB[9*4*8*32];
__device__ __align__(16) float g_wT_in[3*9*64];     // [ic][tap][oc]
__device__ __align__(16) float g_wT_out[64*9*4];    // [ic][tap][oc pad4]
__device__ float g_bf_in[64];
__device__ float g_bf_h [64];
__device__ float g_bf_out[4];

// ================= helpers =================
__device__ __forceinline__ float selu_f(float x) {
    return x > 0.f ? 1.0507009873554805f * x
                   : 1.7580993408473766f * expm1f(x);
}
__device__ __forceinline__ unsigned smem_u32(const void* p) {
    unsigned a;
    asm("{ .reg .u64 t; cvta.to.shared.u64 t, %1; cvt.u32.u64 %0, t; }" : "=r"(a) : "l"(p));
    return a;
}
#define SWZ128(o) ((o) ^ (((o) >> 3) & 0x70))

__device__ __forceinline__ void ldm4(unsigned* r, unsigned addr) {
    asm volatile("ldmatrix.sync.aligned.m8n8.x4.shared.b16 {%0,%1,%2,%3}, [%4];"
        : "=r"(r[0]), "=r"(r[1]), "=r"(r[2]), "=r"(r[3]) : "r"(addr));
}
__device__ __forceinline__ void mma16816(float* d, const unsigned* a, unsigned b0, unsigned b1) {
    asm volatile("mma.sync.aligned.m16n8k16.row.col.f32.bf16.bf16.f32 "
        "{%0,%1,%2,%3}, {%4,%5,%6,%7}, {%8,%9}, {%0,%1,%2,%3};"
        : "+f"(d[0]), "+f"(d[1]), "+f"(d[2]), "+f"(d[3])
        : "r"(a[0]), "r"(a[1]), "r"(a[2]), "r"(a[3]), "r"(b0), "r"(b1));
}
__device__ __forceinline__ unsigned pack_bf2(float a, float b) {
    __nv_bfloat16 ha = __float2bfloat16_rn(a);
    __nv_bfloat16 hb = __float2bfloat16_rn(b);
    return (unsigned)reinterpret_cast<unsigned short&>(ha)
         | ((unsigned)reinterpret_cast<unsigned short&>(hb) << 16);
}

// ================= prep: BN fold + fragment-order weight build =================
__global__ void prep_kernel(
    const float* __restrict__ w_in, const float* __restrict__ b_in,
    const float* __restrict__ g_in, const float* __restrict__ be_in,
    const float* __restrict__ m_in, const float* __restrict__ v_in,
    const float* __restrict__ w_h,  const float* __restrict__ b_h,
    const float* __restrict__ g_h,  const float* __restrict__ be_h,
    const float* __restrict__ m_h,  const float* __restrict__ v_h,
    const float* __restrict__ w_out,const float* __restrict__ b_out,
    const float* __restrict__ g_out,const float* __restrict__ be_out,
    const float* __restrict__ m_out,const float* __restrict__ v_out)
{
    int tid = blockIdx.x * blockDim.x + threadIdx.x;
    int stride = gridDim.x * blockDim.x;
    // B fragments: entry = (((tap*4 + ks)*8 + ntile)*32 + lane)
    // lane L, reg pair: n = ntile*8 + (L>>2); ic0 = ks*16 + (L&3)*2; second reg ic0+8
    for (int i = tid; i < 9*4*8*32; i += stride) {
        int lane  = i & 31;
        int r     = i >> 5;
        int ntile = r & 7;  r >>= 3;
        int ks    = r & 3;
        int tap   = r >> 2;
        int n   = ntile*8 + (lane >> 2);
        int ic0 = ks*16 + (lane & 3)*2;
        float s = g_h[n] * rsqrtf(v_h[n] + EPS_);
        float wv[4];
        wv[0] = w_h[(n*64 + ic0    )*9 + tap] * s;
        wv[1] = w_h[(n*64 + ic0 + 1)*9 + tap] * s;
        wv[2] = w_h[(n*64 + ic0 + 8)*9 + tap] * s;
        wv[3] = w_h[(n*64 + ic0 + 9)*9 + tap] * s;
        __nv_bfloat16 hh[4]; float ll[4];
        #pragma unroll
        for (int q = 0; q < 4; q++) {
            hh[q] = __float2bfloat16_rn(wv[q]);
            ll[q] = wv[q] - __bfloat162float(hh[q]);
        }
        uint4 o;
        o.x = (unsigned)reinterpret_cast<unsigned short&>(hh[0])
            | ((unsigned)reinterpret_cast<unsigned short&>(hh[1]) << 16);
        o.y = (unsigned)reinterpret_cast<unsigned short&>(hh[2])
            | ((unsigned)reinterpret_cast<unsigned short&>(hh[3]) << 16);
        o.z = pack_bf2(ll[0], ll[1]);
        o.w = pack_bf2(ll[2], ll[3]);
        g_wfragB[i] = o;
    }
    for (int i = tid; i < 64*27; i += stride) {
        int oc = i / 27; int rem = i - oc*27;
        int ic = rem / 9; int t = rem - ic*9;
        float s = g_in[oc] * rsqrtf(v_in[oc] + EPS_);
        g_wT_in[(ic*9+t)*64 + oc] = w_in[i] * s;
    }
    for (int i = tid; i < 3*576; i += stride) {
        int oc = i / 576; int rem = i - oc*576;
        int ic = rem / 9; int t = rem - ic*9;
        float s = g_out[oc] * rsqrtf(v_out[oc] + EPS_);
        g_wT_out[(ic*9+t)*4 + oc] = w_out[i] * s;
    }
    if (tid < 64) {
        g_bf_in[tid] = (b_in[tid] - m_in[tid]) * (g_in[tid]*rsqrtf(v_in[tid]+EPS_)) + be_in[tid];
        g_bf_h[tid]  = (b_h[tid]  - m_h[tid])  * (g_h[tid] *rsqrtf(v_h[tid] +EPS_)) + be_h[tid];
    }
    if (tid < 3)
        g_bf_out[tid] = (b_out[tid] - m_out[tid]) * (g_out[tid]*rsqrtf(v_out[tid]+EPS_)) + be_out[tid];
}

// ================= layer 0: NCHW X (3ch) -> hi/lo bf16 NHWC 64 =================
__global__ void __launch_bounds__(256) layer_in_kernel(const float* __restrict__ X)
{
    __shared__ __align__(16) float ws[27*64];
    __shared__ float bs[64];
    int tid = threadIdx.x;
    for (int i = tid; i < 27*64; i += 256) ws[i] = g_wT_in[i];
    if (tid < 64) bs[tid] = g_bf_in[tid];
    __syncthreads();

    int b  = blockIdx.z;
    int gy = blockIdx.y * 16 + (tid >> 4);
    int gx = blockIdx.x * 16 + (tid & 15);

    float patch[27];
    #pragma unroll
    for (int ic = 0; ic < 3; ic++)
        #pragma unroll
        for (int ky = 0; ky < 3; ky++)
            #pragma unroll
            for (int kx = 0; kx < 3; kx++) {
                int y = gy + ky - 1, x = gx + kx - 1;
                float v = 0.f;
                if ((unsigned)y < HH && (unsigned)x < WW)
                    v = X[((b*3 + ic)*HH + y)*WW + x];
                patch[(ic*3+ky)*3+kx] = v;
            }

    float acc[64];
    #pragma unroll
    for (int k = 0; k < 64; k++) acc[k] = bs[k];
    #pragma unroll
    for (int q = 0; q < 27; q++) {
        float xv = patch[q];
        const float* wr = &ws[q*64];
        #pragma unroll
        for (int k = 0; k < 64; k += 4) {
            float4 w = *(const float4*)(wr + k);
            acc[k]   += xv*w.x; acc[k+1] += xv*w.y;
            acc[k+2] += xv*w.z; acc[k+3] += xv*w.w;
        }
    }
    size_t pb = (((size_t)(b*HH) + gy)*WW + gx)*64;
    #pragma unroll
    for (int g = 0; g < 8; g++) {
        float v[8];
        #pragma unroll
        for (int c = 0; c < 8; c++) v[c] = selu_f(acc[g*8+c]);
        unsigned uh[4], ul[4];
        #pragma unroll
        for (int c2 = 0; c2 < 4; c2++) {
            float a = v[2*c2], bb = v[2*c2+1];
            __nv_bfloat16 ha = __float2bfloat16_rn(a), hb = __float2bfloat16_rn(bb);
            float la = a - __bfloat162float(ha), lb = bb - __bfloat162float(hb);
            uh[c2] = (unsigned)reinterpret_cast<unsigned short&>(ha)
                   | ((unsigned)reinterpret_cast<unsigned short&>(hb) << 16);
            ul[c2] = pack_bf2(la, lb);
        }
        *(uint4*)(g_hiA + pb + g*8) = make_uint4(uh[0],uh[1],uh[2],uh[3]);
        *(uint4*)(g_loA + pb + g*8) = make_uint4(ul[0],ul[1],ul[2],ul[3]);
    }
}

// ================= hidden layers: mma.sync bf16-split implicit conv =================
// CTA 16x16 px x 64 oc, 8 warps, 2 CTAs/SM. B operands read directly from
// global in fragment order (L2-hot, shared by all CTAs) -> NO syncs in tap loop.
#define SM_BIAS  0
#define SM_X     1024
#define X_SPLIT  41984               /* >= 324px*128B, 1024-aligned */
#define HID_SMEM (SM_X + 2*X_SPLIT)  /* 84992 -> 2 CTAs/SM */
#define PXSTR    68                  /* epilogue f32 stride per pixel */

__global__ void __launch_bounds__(256, 2) hidden_mma_kernel(int flip)
{
    extern __shared__ __align__(1024) unsigned char smem[];
    unsigned sb = smem_u32(smem);
    int tid = threadIdx.x;
    int w = tid >> 5, lane = tid & 31;

    const __nv_bfloat16* __restrict__ shi = flip ? g_hiB : g_hiA;
    const __nv_bfloat16* __restrict__ slo = flip ? g_loB : g_loA;
    __nv_bfloat16* __restrict__ dhi = flip ? g_hiA : g_hiB;
    __nv_bfloat16* __restrict__ dlo = flip ? g_loA : g_loB;

    int b  = blockIdx.z;
    int y0 = blockIdx.y * 16;
    int x0 = blockIdx.x * 16;

    if (tid < 64) ((float*)smem)[tid] = g_bf_h[tid];

    // ---- stage input tile: 2 splits x 18x18 px x 128B, SW128 per tile ----
    for (int i = tid; i < 5184; i += 256) {
        int split = i >= 2592;
        int r = split ? i - 2592 : i;
        int pxi = r >> 3, g = r & 7;
        int iy = pxi / 18, ix = pxi - iy*18;
        int gy = y0 - 1 + iy, gx = x0 - 1 + ix;
        uint4 v = make_uint4(0,0,0,0);
        if ((unsigned)gy < HH && (unsigned)gx < WW) {
            const __nv_bfloat16* sp = (split ? slo : shi) + (((size_t)(b*HH) + gy)*WW + gx)*64;
            v = *((const uint4*)sp + g);
        }
        unsigned rel = (unsigned)(pxi*128 + g*16);
        *(uint4*)(smem + SM_X + split*X_SPLIT + SWZ128(rel)) = v;
    }
    __syncthreads();

    float acc[2][8][4];
    #pragma unroll
    for (int mt = 0; mt < 2; mt++)
        #pragma unroll
        for (int nt = 0; nt < 8; nt++)
            #pragma unroll
            for (int q = 0; q < 4; q++) acc[mt][nt][q] = 0.f;

    int amat = lane >> 3, arow = lane & 7;
    int a_frow = ((amat & 1) << 3) + arow;   // A: fragment row (pixel)
    int a_kg   = amat >> 1;                  // A: k granule (16B)

    const uint4* __restrict__ wf = g_wfragB + lane;

    #pragma unroll 1
    for (int tap = 0; tap < 9; tap++) {
        int dy = tap / 3, dx = tap - dy*3;
        #pragma unroll
        for (int ks = 0; ks < 4; ks++) {
            unsigned Ah[2][4], Al[2][4];
            #pragma unroll
            for (int mt = 0; mt < 2; mt++) {
                int iy  = 2*w + mt + dy;
                int pxi = iy*18 + dx + a_frow;
                unsigned rel = (unsigned)(pxi*128 + ks*32 + a_kg*16);
                rel ^= (unsigned)((pxi & 7) << 4);
                ldm4(Ah[mt], sb + SM_X + rel);
                ldm4(Al[mt], sb + SM_X + X_SPLIT + rel);
            }
            const uint4* wrow = wf + (tap*4 + ks)*8*32;
            #pragma unroll
            for (int nt = 0; nt < 8; nt++) {
                uint4 b4 = wrow[nt*32];
                #pragma unroll
                for (int mt = 0; mt < 2; mt++) {
                    float* ac = acc[mt][nt];
                    mma16816(ac, Ah[mt], b4.x, b4.y);   // xh*wh
                    mma16816(ac, Ah[mt], b4.z, b4.w);   // xh*wl
                    mma16816(ac, Al[mt], b4.x, b4.y);   // xl*wh
                }
            }
        }
    }

    // ---- epilogue: fragments -> smem f32 (padded) -> bias+selu -> hi/lo bf16 ----
    __syncthreads();   // all warps done reading xs; reuse as f32 staging
    float* fs = (float*)(smem + SM_X);
    #pragma unroll
    for (int mt = 0; mt < 2; mt++) {
        int prow = 2*w + mt;
        #pragma unroll
        for (int nt = 0; nt < 8; nt++) {
            int oc = nt*8 + 2*(lane & 3);
            int p0 = (prow*16 + (lane >> 2)) * PXSTR + oc;
            int p1 = (prow*16 + (lane >> 2) + 8) * PXSTR + oc;
            *(float2*)&fs[p0] = make_float2(acc[mt][nt][0], acc[mt][nt][1]);
            *(float2*)&fs[p1] = make_float2(acc[mt][nt][2], acc[mt][nt][3]);
        }
    }
    __syncthreads();

    {
        const float* bias = (const float*)smem;
        int ly = tid >> 4, lx = tid & 15;
        const float* fp = fs + tid * PXSTR;
        size_t pb = (((size_t)(b*HH) + (y0 + ly))*WW + (x0 + lx))*64;
        #pragma unroll
        for (int g = 0; g < 8; g++) {
            float4 v0 = *(const float4*)(fp + g*8);
            float4 v1 = *(const float4*)(fp + g*8 + 4);
            float v[8] = {v0.x, v0.y, v0.z, v0.w, v1.x, v1.y, v1.z, v1.w};
            unsigned uh[4], ul[4];
            #pragma unroll
            for (int c2 = 0; c2 < 4; c2++) {
                float a = selu_f(v[2*c2]   + bias[g*8 + 2*c2]);
                float c = selu_f(v[2*c2+1] + bias[g*8 + 2*c2 + 1]);
                __nv_bfloat16 ha = __float2bfloat16_rn(a), hc = __float2bfloat16_rn(c);
                float la = a - __bfloat162float(ha), lc = c - __bfloat162float(hc);
                uh[c2] = (unsigned)reinterpret_cast<unsigned short&>(ha)
                       | ((unsigned)reinterpret_cast<unsigned short&>(hc) << 16);
                ul[c2] = pack_bf2(la, lc);
            }
            *(uint4*)(dhi + pb + g*8) = make_uint4(uh[0],uh[1],uh[2],uh[3]);
            *(uint4*)(dlo + pb + g*8) = make_uint4(ul[0],ul[1],ul[2],ul[3]);
        }
    }
}

// ================= output layer + zero-interpolation residual =================
#define XP2 20
__global__ void __launch_bounds__(256) layer_out_kernel(const float* __restrict__ X,
                                                        float* __restrict__ out)
{
    __shared__ __align__(16) float xs[16*18*XP2];
    __shared__ __align__(16) float ws[576*4];
    int tid = threadIdx.x;
    for (int i = tid; i < 2304; i += 256) ws[i] = g_wT_out[i];

    int b   = blockIdx.z;
    int ty0 = blockIdx.y*16, tx0 = blockIdx.x*16;
    int row = tid >> 4, col = tid & 15;
    float a0 = 0.f, a1 = 0.f, a2 = 0.f;

    for (int c0 = 0; c0 < 64; c0 += 16) {
        __syncthreads();
        for (int i = tid; i < 1296; i += 256) {
            int q  = i & 3;
            int p  = i >> 2;
            int yy = p / 18, xx = p - yy*18;
            int gy = ty0 + yy - 1, gx = tx0 + xx - 1;
            float v0=0.f, v1=0.f, v2=0.f, v3=0.f;
            if ((unsigned)gy < HH && (unsigned)gx < WW) {
                size_t idx = (((size_t)(b*HH) + gy)*WW + gx)*64 + c0 + q*4;
                uint2 hv = *(const uint2*)(g_hiA + idx);
                uint2 lv = *(const uint2*)(g_loA + idx);
                __nv_bfloat162 h0 = *(__nv_bfloat162*)&hv.x, h1 = *(__nv_bfloat162*)&hv.y;
                __nv_bfloat162 l0 = *(__nv_bfloat162*)&lv.x, l1 = *(__nv_bfloat162*)&lv.y;
                v0 = __bfloat162float(h0.x) + __bfloat162float(l0.x);
                v1 = __bfloat162float(h0.y) + __bfloat162float(l0.y);
                v2 = __bfloat162float(h1.x) + __bfloat162float(l1.x);
                v3 = __bfloat162float(h1.y) + __bfloat162float(l1.y);
            }
            float* d = xs + (q*4)*(18*XP2) + yy*XP2 + xx;
            d[0] = v0; d[18*XP2] = v1; d[2*18*XP2] = v2; d[3*18*XP2] = v3;
        }
        __syncthreads();
        for (int icL = 0; icL < 16; icL++) {
            const float* xpl = xs + icL*18*XP2 + row*XP2 + col;
            const float* wr  = ws + (c0+icL)*36;
            #pragma unroll
            for (int tap = 0; tap < 9; tap++) {
                float xv = xpl[(tap/3)*XP2 + (tap%3)];
                float4 w = *(const float4*)(wr + tap*4);
                a0 += xv*w.x; a1 += xv*w.y; a2 += xv*w.z;
            }
        }
    }
    float vv[3];
    vv[0] = selu_f(a0 + g_bf_out[0]);
    vv[1] = selu_f(a1 + g_bf_out[1]);
    vv[2] = selu_f(a2 + g_bf_out[2]);

    int gy = ty0 + row, gx = tx0 + col;
    #pragma unroll
    for (int c = 0; c < 3; c++) {
        size_t idx = ((size_t)(b*3+c)*HH + gy)*WW + gx;
        float xc = X[idx];
        float res;
        if (xc == 0.f) {
            float lf = (gx > 0)    ? X[idx-1]  : 0.f;
            float rt = (gx < WW-1) ? X[idx+1]  : 0.f;
            float tp = (gy > 0)    ? X[idx-WW] : 0.f;
            float bt = (gy < HH-1) ? X[idx+WW] : 0.f;
            float sum = lf + rt + tp + bt;
            float cnt = (float)(lf>0.f) + (float)(rt>0.f) + (float)(tp>0.f) + (float)(bt>0.f);
            res = (cnt > 0.f) ? sum / cnt : 0.f;
        } else {
            res = xc;
        }
        out[idx] = vv[c] + res;
    }
}

// ================= launch =================
extern "C" void kernel_launch(void* const* d_in, const int* in_sizes, int n_in,
                              void* d_out, int out_size)
{
    const float* X      = (const float*)d_in[0];
    const float* w_in   = (const float*)d_in[1];
    const float* b_in   = (const float*)d_in[2];
    const float* g_in   = (const float*)d_in[3];
    const float* be_in  = (const float*)d_in[4];
    const float* m_in   = (const float*)d_in[5];
    const float* v_in   = (const float*)d_in[6];
    const float* w_h    = (const float*)d_in[7];
    const float* b_h    = (const float*)d_in[8];
    const float* g_h    = (const float*)d_in[9];
    const float* be_h   = (const float*)d_in[10];
    const float* m_h    = (const float*)d_in[11];
    const float* v_h    = (const float*)d_in[12];
    const float* w_out  = (const float*)d_in[13];
    const float* b_out  = (const float*)d_in[14];
    const float* g_out  = (const float*)d_in[15];
    const float* be_out = (const float*)d_in[16];
    const float* m_out  = (const float*)d_in[17];
    const float* v_out  = (const float*)d_in[18];
    float* out = (float*)d_out;

    cudaFuncSetAttribute(hidden_mma_kernel,
                         cudaFuncAttributeMaxDynamicSharedMemorySize, HID_SMEM);

    prep_kernel<<<144, 256>>>(w_in, b_in, g_in, be_in, m_in, v_in,
                              w_h, b_h, g_h, be_h, m_h, v_h,
                              w_out, b_out, g_out, be_out, m_out, v_out);
    layer_in_kernel<<<dim3(16,16,4), 256>>>(X);
    int flip = 0;
    for (int l = 0; l < 18; l++) {
        hidden_mma_kernel<<<dim3(16,16,4), 256, HID_SMEM>>>(flip);
        flip ^= 1;
    }
    layer_out_kernel<<<dim3(16,16,4), 256>>>(X, out);
}